// round 16
// baseline (speedup 1.0000x reference)
#include <cuda_runtime.h>

// ---------------------------------------------------------------------------
// RestorationLoss: 1 - SSIM(x,y) + MSE(x,y), single fused kernel.
//   * separable 11-tap Gaussian; packed f32x2 fields (s,d),(s^2,d^2) (FFMA2)
//   * NBY=5 / TH=103 / V=13; skewed conflict-free h-buffer; L2 prefetch
//   * NEW: s/d field formation fully packed (add2 + fma2(-1)), -16 fma/unit
//   * deterministic fixed-point atomic reduction + last-block finalize/reset
// ---------------------------------------------------------------------------

#define IMG     512
#define TW      32
#define TH      103
#define HALO    5
#define LH      113                // h rows produced (TH + 2*HALO)
#define LHBUF   114                // + 1 zeroed guard row (row 113)
#define HSTR    72                 // ull row stride (576B == 64 mod 128: CF)
#define HUNITS  (LH*4)             // 452
#define NBX     (IMG/TW)           // 16
#define NBY     5                  // ceil(512/103)
#define NPL     48
#define NBLOCKS (NBX*NBY*NPL)      // 3840
#define NPIX    (16.0*3.0*512.0*512.0)
#define FXS     268435456.0        // 2^28
#define SMEMB   (LHBUF*HSTR*8)     // 65664 bytes (dynamic)
#define VOUT    13

#define C1f 1.0e-4f
#define C2f 9.0e-4f

typedef unsigned long long ull;

#define SKEW(c) (2*(c) + 2*((c) >> 3))
#define NEG2    0xBF800000BF800000ull   // packed (-1.0f, -1.0f)

__constant__ float2 GW2[6] = {
    {0.00102838f, 0.00102838f},
    {0.00759876f, 0.00759876f},
    {0.03600077f, 0.03600077f},
    {0.10936069f, 0.10936069f},
    {0.21300554f, 0.21300554f},
    {0.26601172f, 0.26601172f}
};

__device__ ull g_acc[2] = {0ull, 0ull};
__device__ unsigned g_count = 0u;

static __device__ __forceinline__ ull fma2(ull a, ull b, ull c) {
    ull r; asm("fma.rn.f32x2 %0, %1, %2, %3;" : "=l"(r) : "l"(a), "l"(b), "l"(c));
    return r;
}
static __device__ __forceinline__ ull add2(ull a, ull b) {
    ull r; asm("add.rn.f32x2 %0, %1, %2;" : "=l"(r) : "l"(a), "l"(b));
    return r;
}
static __device__ __forceinline__ ull mul2(ull a, ull b) {
    ull r; asm("mul.rn.f32x2 %0, %1, %2;" : "=l"(r) : "l"(a), "l"(b));
    return r;
}
static __device__ __forceinline__ ull pack2(float lo, float hi) {
    ull r; asm("mov.b64 %0, {%1,%2};" : "=l"(r) : "f"(lo), "f"(hi));
    return r;
}
static __device__ __forceinline__ float2 unpack2(ull v) {
    float2 r; asm("mov.b64 {%0,%1}, %2;" : "=f"(r.x), "=f"(r.y) : "l"(v));
    return r;
}
static __device__ __forceinline__ float frcp(float a) {
    float r; asm("rcp.approx.ftz.f32 %0, %1;" : "=f"(r) : "f"(a));
    return r;
}
static __device__ __forceinline__ void pf_l2(const void* p) {
    asm volatile("prefetch.global.L2 [%0];" :: "l"(p));
}

__global__ __launch_bounds__(256, 3)
void loss_kernel(const float* __restrict__ x, const float* __restrict__ y,
                 float* __restrict__ out)
{
    extern __shared__ ull h[];         // [LHBUF][HSTR], skewed columns
    __shared__ float red[16];
    __shared__ int  s_last;

    const int tid   = threadIdx.x;
    const int bx    = blockIdx.x;
    const int by    = blockIdx.y;
    const int plane = blockIdx.z;
    const int base  = bx * TW;
    const int r0    = by * TH - HALO;

    const float* __restrict__ xp = x + (size_t)plane * (IMG * IMG);
    const float* __restrict__ yp = y + (size_t)plane * (IMG * IMG);

    ull gw[6];
    #pragma unroll
    for (int k = 0; k < 6; k++) gw[k] = ((const ull*)GW2)[k];
    #define WK(k) gw[(k) <= 5 ? (k) : 10 - (k)]

    // ---- zero the guard row (113) ----
    if (tid < HSTR) h[LH * HSTR + tid] = 0ull;

    // ---- prefetch iter2 inputs to L2 (units 256..451) ----
    if (tid < 196) {
        const int u2  = 256 + tid;
        const int r2  = u2 >> 2;
        const int q2  = u2 & 3;
        const int gr2 = r0 + r2;
        if ((unsigned)gr2 < IMG) {
            const int cA = base + 8 * q2 - 4;
            if ((unsigned)cA < IMG) {
                pf_l2(xp + gr2 * IMG + cA);
                pf_l2(yp + gr2 * IMG + cA);
            }
            const int cB = cA + 16;
            if ((unsigned)cB < IMG) {
                pf_l2(xp + gr2 * IMG + cB);
                pf_l2(yp + gr2 * IMG + cB);
            }
        }
    }

    // ---- horizontal pass: 8 outputs/unit; 452 units = 256 + 196(+28) ----
    ull mse2 = 0ull;                  // packed (junk, sum d^2)
    #pragma unroll
    for (int iter = 0; iter < 2; iter++) {
        if (iter == 1 && tid >= 224) break;   // warp 7 skips: warp-uniform
        const int u      = iter * 256 + tid;
        const bool valid = (u < HUNITS);
        const int uu     = valid ? u : (HUNITS - 1);
        const int r      = uu >> 2;
        const int q      = uu & 3;
        const int gr     = r0 + r;
        const bool rowok = ((unsigned)gr < IMG);
        const int c0c    = base + 8 * q;
        const float* xrow = xp + gr * IMG;
        const float* yrow = yp + gr * IMG;

        float4 X[4], Y[4];
        #pragma unroll
        for (int m = 0; m < 4; m++) {
            const int col = c0c - 4 + 4 * m;
            const bool ok = rowok & ((unsigned)col < IMG);
            X[m] = ok ? __ldg((const float4*)(xrow + col)) : make_float4(0.f,0.f,0.f,0.f);
            Y[m] = ok ? __ldg((const float4*)(yrow + col)) : make_float4(0.f,0.f,0.f,0.f);
        }
        float ex = 0.f, ey = 0.f, fxe = 0.f, fye = 0.f;
        if (q == 0) {
            const int col = base - 8;
            if (rowok & (col >= 0)) {
                ex = __ldg((const float4*)(xrow + col)).w;
                ey = __ldg((const float4*)(yrow + col)).w;
            }
        }
        if (q == 3) {
            const int col = c0c + 12;
            if (rowok & ((unsigned)col < IMG)) {
                fxe = __ldg((const float4*)(xrow + col)).x;
                fye = __ldg((const float4*)(yrow + col)).x;
            }
        }

        // packed (s,d) formation: add2 / fma2(-1) per column pair
        ull w[18];
        #pragma unroll
        for (int m = 0; m < 4; m++) {
            ull x01 = pack2(X[m].x, X[m].y);
            ull x23 = pack2(X[m].z, X[m].w);
            ull y01 = pack2(Y[m].x, Y[m].y);
            ull y23 = pack2(Y[m].z, Y[m].w);
            ull s01 = add2(x01, y01);
            ull d01 = fma2(y01, NEG2, x01);
            ull s23 = add2(x23, y23);
            ull d23 = fma2(y23, NEG2, x23);
            float2 sa = unpack2(s01), da = unpack2(d01);
            float2 sb = unpack2(s23), db = unpack2(d23);
            w[1 + 4*m + 0] = pack2(sa.x, da.x);
            w[1 + 4*m + 1] = pack2(sa.y, da.y);
            w[1 + 4*m + 2] = pack2(sb.x, db.x);
            w[1 + 4*m + 3] = pack2(sb.y, db.y);
        }
        ull wl = __shfl_up_sync(0xffffffffu, w[8], 1);
        ull wr = __shfl_down_sync(0xffffffffu, w[9], 1);
        if (q == 0) wl = pack2(ex + ey, ex - ey);
        if (q == 3) wr = pack2(fxe + fye, fxe - fye);
        w[0]  = wl;
        w[17] = wr;

        // MSE: h row r -> tile output row r-HALO; unique owner per pixel
        const bool mrowok = valid & (r >= HALO) & (r < HALO + TH) & rowok;
        if (mrowok) {
            #pragma unroll
            for (int t = 5; t <= 12; t++)
                mse2 = fma2(w[t], w[t], mse2);
        }

        ull a1[8] = {0,0,0,0,0,0,0,0};
        ull a2[8] = {0,0,0,0,0,0,0,0};
        #pragma unroll
        for (int t = 0; t < 18; t++) {
            ull v  = w[t];
            ull v2 = mul2(v, v);
            #pragma unroll
            for (int o = 0; o < 8; o++) {
                const int k = t - o;
                if (k >= 0 && k <= 10) {
                    a1[o] = fma2(v,  WK(k), a1[o]);
                    a2[o] = fma2(v2, WK(k), a2[o]);
                }
            }
        }
        if (valid) {
            ull* hrow = h + r * HSTR;
            #pragma unroll
            for (int o = 0; o < 8; o++)
                *((ulonglong2*)(hrow + SKEW(8*q + o))) = make_ulonglong2(a1[o], a2[o]);
        }
    }
    float mse_acc = unpack2(mse2).y;
    __syncthreads();

    // ---- vertical pass: 1 column x 13 consecutive rows per thread ----
    const int c  = tid & 31;
    const int rb = (tid >> 5) * VOUT;  // 0,13,...,91 (reads rows rb..rb+22)

    ull b1[VOUT] = {0,0,0,0,0,0,0,0,0,0,0,0,0};
    ull b2[VOUT] = {0,0,0,0,0,0,0,0,0,0,0,0,0};
    const ull* vp = h + rb * HSTR + SKEW(c);
    #pragma unroll
    for (int j = 0; j < VOUT + 10; j++) {
        ulonglong2 u = *((const ulonglong2*)(vp + j * HSTR));
        #pragma unroll
        for (int o = 0; o < VOUT; o++) {
            const int k = j - o;
            if (k >= 0 && k <= 10) {
                b1[o] = fma2(u.x, WK(k), b1[o]);
                b2[o] = fma2(u.y, WK(k), b2[o]);
            }
        }
    }

    // ---- SSIM epilogue: batch 4 divisions per MUFU.RCP ----
    float ssim_acc = 0.f;
    float Nacc = 0.f, Dacc = 1.f;
    int   cnt = 0;
    #pragma unroll
    for (int o = 0; o < VOUT; o++) {
        const int tr  = rb + o;
        const int gro = by * TH + tr;
        if (tr < TH && gro < IMG) {
            float2 m = unpack2(b1[o]);   // (mu_s, mu_d)
            float2 e = unpack2(b2[o]);   // (E[s^2], E[d^2])
            float mus2 = m.x * m.x;
            float mud2 = m.y * m.y;
            float mu12   = 0.25f * (mus2 - mud2);
            float musum  = 0.5f  * (mus2 + mud2);
            float sig12  = 0.25f * (e.x - e.y) - mu12;
            float sigsum = 0.5f  * (e.x + e.y) - musum;
            float num = (2.f * mu12 + C1f) * (2.f * sig12 + C2f);
            float den = (musum + C1f) * (sigsum + C2f);
            Nacc = Nacc * den + num * Dacc;
            Dacc = Dacc * den;
            cnt++;
            if (cnt == 4) {
                ssim_acc = fmaf(Nacc, frcp(Dacc), ssim_acc);
                Nacc = 0.f; Dacc = 1.f; cnt = 0;
            }
        }
    }
    if (cnt > 0)
        ssim_acc = fmaf(Nacc, frcp(Dacc), ssim_acc);

    // ---- block reduction -> deterministic fixed-point atomics ----
    #pragma unroll
    for (int off = 16; off > 0; off >>= 1) {
        ssim_acc += __shfl_down_sync(0xffffffffu, ssim_acc, off);
        mse_acc  += __shfl_down_sync(0xffffffffu, mse_acc,  off);
    }
    if ((tid & 31) == 0) {
        red[tid >> 5]       = ssim_acc;
        red[8 + (tid >> 5)] = mse_acc;
    }
    __syncthreads();
    if (tid == 0) {
        float ss = 0.f, mm = 0.f;
        #pragma unroll
        for (int w2 = 0; w2 < 8; w2++) { ss += red[w2]; mm += red[8 + w2]; }
        atomicAdd(&g_acc[0], (ull)__double2ll_rn((double)ss * FXS));
        atomicAdd(&g_acc[1], (ull)__double2ll_rn((double)mm * FXS));
        __threadfence();
        unsigned t = atomicAdd(&g_count, 1u);
        s_last = (t == NBLOCKS - 1);
    }
    __syncthreads();

    // ---- last block finalizes and resets for next graph replay ----
    if (s_last && tid == 0) {
        __threadfence();
        ull a0  = atomicExch(&g_acc[0], 0ull);
        ull a1v = atomicExch(&g_acc[1], 0ull);
        atomicExch(&g_count, 0u);
        double inv = 1.0 / (NPIX * FXS);
        double ss = (double)(long long)a0 * inv;
        double mm = (double)(long long)a1v * inv;
        out[0] = (float)(1.0 - ss + mm);
    }
}

extern "C" void kernel_launch(void* const* d_in, const int* in_sizes, int n_in,
                              void* d_out, int out_size)
{
    const float* x = (const float*)d_in[0];
    const float* y = (const float*)d_in[1];
    float* out = (float*)d_out;

    cudaFuncSetAttribute(loss_kernel,
                         cudaFuncAttributeMaxDynamicSharedMemorySize, SMEMB);

    dim3 grid(NBX, NBY, NPL);   // (16, 5, 48) = 3840 blocks
    loss_kernel<<<grid, 256, SMEMB>>>(x, y, out);
}

// round 17
// speedup vs baseline: 1.1171x; 1.1171x over previous
#include <cuda_runtime.h>

// ---------------------------------------------------------------------------
// RestorationLoss: 1 - SSIM(x,y) + MSE(x,y), single fused kernel.
// FINAL (= R15 best, 72.4us): R16's packed s/d formation reverted — the lane
// re-pairing cost ~24 alu MOV/PRMT per unit (alu 17->39%) vs 16 fma saved.
//   * separable 11-tap Gaussian; packed f32x2 fields (s,d),(s^2,d^2) (FFMA2)
//   * NBY=5 / TH=103 / V=13; skewed conflict-free h-buffer; L2 prefetch
//   * h-pass: 452 units = 256 + 196(+28 ghost) over 2 rounds
//   * SSIM divisions batched 4x per MUFU.RCP
//   * deterministic fixed-point atomic reduction + last-block finalize/reset
// ---------------------------------------------------------------------------

#define IMG     512
#define TW      32
#define TH      103
#define HALO    5
#define LH      113                // h rows produced (TH + 2*HALO)
#define LHBUF   114                // + 1 zeroed guard row (row 113)
#define HSTR    72                 // ull row stride (576B == 64 mod 128: CF)
#define HUNITS  (LH*4)             // 452
#define NBX     (IMG/TW)           // 16
#define NBY     5                  // ceil(512/103)
#define NPL     48
#define NBLOCKS (NBX*NBY*NPL)      // 3840
#define NPIX    (16.0*3.0*512.0*512.0)
#define FXS     268435456.0        // 2^28
#define SMEMB   (LHBUF*HSTR*8)     // 65664 bytes (dynamic)
#define VOUT    13

#define C1f 1.0e-4f
#define C2f 9.0e-4f

typedef unsigned long long ull;

#define SKEW(c) (2*(c) + 2*((c) >> 3))

__constant__ float2 GW2[6] = {
    {0.00102838f, 0.00102838f},
    {0.00759876f, 0.00759876f},
    {0.03600077f, 0.03600077f},
    {0.10936069f, 0.10936069f},
    {0.21300554f, 0.21300554f},
    {0.26601172f, 0.26601172f}
};

__device__ ull g_acc[2] = {0ull, 0ull};
__device__ unsigned g_count = 0u;

static __device__ __forceinline__ ull fma2(ull a, ull b, ull c) {
    ull r; asm("fma.rn.f32x2 %0, %1, %2, %3;" : "=l"(r) : "l"(a), "l"(b), "l"(c));
    return r;
}
static __device__ __forceinline__ ull mul2(ull a, ull b) {
    ull r; asm("mul.rn.f32x2 %0, %1, %2;" : "=l"(r) : "l"(a), "l"(b));
    return r;
}
static __device__ __forceinline__ ull pack2(float lo, float hi) {
    ull r; asm("mov.b64 %0, {%1,%2};" : "=l"(r) : "f"(lo), "f"(hi));
    return r;
}
static __device__ __forceinline__ float2 unpack2(ull v) {
    float2 r; asm("mov.b64 {%0,%1}, %2;" : "=f"(r.x), "=f"(r.y) : "l"(v));
    return r;
}
static __device__ __forceinline__ float frcp(float a) {
    float r; asm("rcp.approx.ftz.f32 %0, %1;" : "=f"(r) : "f"(a));
    return r;
}
static __device__ __forceinline__ void pf_l2(const void* p) {
    asm volatile("prefetch.global.L2 [%0];" :: "l"(p));
}

__global__ __launch_bounds__(256, 3)
void loss_kernel(const float* __restrict__ x, const float* __restrict__ y,
                 float* __restrict__ out)
{
    extern __shared__ ull h[];         // [LHBUF][HSTR], skewed columns
    __shared__ float red[16];
    __shared__ int  s_last;

    const int tid   = threadIdx.x;
    const int bx    = blockIdx.x;
    const int by    = blockIdx.y;
    const int plane = blockIdx.z;
    const int base  = bx * TW;
    const int r0    = by * TH - HALO;

    const float* __restrict__ xp = x + (size_t)plane * (IMG * IMG);
    const float* __restrict__ yp = y + (size_t)plane * (IMG * IMG);

    ull gw[6];
    #pragma unroll
    for (int k = 0; k < 6; k++) gw[k] = ((const ull*)GW2)[k];
    #define WK(k) gw[(k) <= 5 ? (k) : 10 - (k)]

    // ---- zero the guard row (113) ----
    if (tid < HSTR) h[LH * HSTR + tid] = 0ull;

    // ---- prefetch iter2 inputs to L2 (units 256..451) ----
    if (tid < 196) {
        const int u2  = 256 + tid;
        const int r2  = u2 >> 2;
        const int q2  = u2 & 3;
        const int gr2 = r0 + r2;
        if ((unsigned)gr2 < IMG) {
            const int cA = base + 8 * q2 - 4;
            if ((unsigned)cA < IMG) {
                pf_l2(xp + gr2 * IMG + cA);
                pf_l2(yp + gr2 * IMG + cA);
            }
            const int cB = cA + 16;
            if ((unsigned)cB < IMG) {
                pf_l2(xp + gr2 * IMG + cB);
                pf_l2(yp + gr2 * IMG + cB);
            }
        }
    }

    // ---- horizontal pass: 8 outputs/unit; 452 units = 256 + 196(+28) ----
    ull mse2 = 0ull;                  // packed (junk, sum d^2)
    #pragma unroll
    for (int iter = 0; iter < 2; iter++) {
        if (iter == 1 && tid >= 224) break;   // warp 7 skips: warp-uniform
        const int u      = iter * 256 + tid;
        const bool valid = (u < HUNITS);
        const int uu     = valid ? u : (HUNITS - 1);
        const int r      = uu >> 2;
        const int q      = uu & 3;
        const int gr     = r0 + r;
        const bool rowok = ((unsigned)gr < IMG);
        const int c0c    = base + 8 * q;
        const float* xrow = xp + gr * IMG;
        const float* yrow = yp + gr * IMG;

        float4 X[4], Y[4];
        #pragma unroll
        for (int m = 0; m < 4; m++) {
            const int col = c0c - 4 + 4 * m;
            const bool ok = rowok & ((unsigned)col < IMG);
            X[m] = ok ? __ldg((const float4*)(xrow + col)) : make_float4(0.f,0.f,0.f,0.f);
            Y[m] = ok ? __ldg((const float4*)(yrow + col)) : make_float4(0.f,0.f,0.f,0.f);
        }
        float ex = 0.f, ey = 0.f, fxe = 0.f, fye = 0.f;
        if (q == 0) {
            const int col = base - 8;
            if (rowok & (col >= 0)) {
                ex = __ldg((const float4*)(xrow + col)).w;
                ey = __ldg((const float4*)(yrow + col)).w;
            }
        }
        if (q == 3) {
            const int col = c0c + 12;
            if (rowok & ((unsigned)col < IMG)) {
                fxe = __ldg((const float4*)(xrow + col)).x;
                fye = __ldg((const float4*)(yrow + col)).x;
            }
        }

        ull w[18];
        #pragma unroll
        for (int m = 0; m < 4; m++) {
            const float* fxp = (const float*)&X[m];
            const float* fyp = (const float*)&Y[m];
            #pragma unroll
            for (int e = 0; e < 4; e++)
                w[1 + 4*m + e] = pack2(fxp[e] + fyp[e], fxp[e] - fyp[e]);
        }
        ull wl = __shfl_up_sync(0xffffffffu, w[8], 1);
        ull wr = __shfl_down_sync(0xffffffffu, w[9], 1);
        if (q == 0) wl = pack2(ex + ey, ex - ey);
        if (q == 3) wr = pack2(fxe + fye, fxe - fye);
        w[0]  = wl;
        w[17] = wr;

        // MSE: h row r -> tile output row r-HALO; unique owner per pixel
        const bool mrowok = valid & (r >= HALO) & (r < HALO + TH) & rowok;
        if (mrowok) {
            #pragma unroll
            for (int t = 5; t <= 12; t++)
                mse2 = fma2(w[t], w[t], mse2);
        }

        ull a1[8] = {0,0,0,0,0,0,0,0};
        ull a2[8] = {0,0,0,0,0,0,0,0};
        #pragma unroll
        for (int t = 0; t < 18; t++) {
            ull v  = w[t];
            ull v2 = mul2(v, v);
            #pragma unroll
            for (int o = 0; o < 8; o++) {
                const int k = t - o;
                if (k >= 0 && k <= 10) {
                    a1[o] = fma2(v,  WK(k), a1[o]);
                    a2[o] = fma2(v2, WK(k), a2[o]);
                }
            }
        }
        if (valid) {
            ull* hrow = h + r * HSTR;
            #pragma unroll
            for (int o = 0; o < 8; o++)
                *((ulonglong2*)(hrow + SKEW(8*q + o))) = make_ulonglong2(a1[o], a2[o]);
        }
    }
    float mse_acc = unpack2(mse2).y;
    __syncthreads();

    // ---- vertical pass: 1 column x 13 consecutive rows per thread ----
    const int c  = tid & 31;
    const int rb = (tid >> 5) * VOUT;  // 0,13,...,91 (reads rows rb..rb+22)

    ull b1[VOUT] = {0,0,0,0,0,0,0,0,0,0,0,0,0};
    ull b2[VOUT] = {0,0,0,0,0,0,0,0,0,0,0,0,0};
    const ull* vp = h + rb * HSTR + SKEW(c);
    #pragma unroll
    for (int j = 0; j < VOUT + 10; j++) {
        ulonglong2 u = *((const ulonglong2*)(vp + j * HSTR));
        #pragma unroll
        for (int o = 0; o < VOUT; o++) {
            const int k = j - o;
            if (k >= 0 && k <= 10) {
                b1[o] = fma2(u.x, WK(k), b1[o]);
                b2[o] = fma2(u.y, WK(k), b2[o]);
            }
        }
    }

    // ---- SSIM epilogue: batch 4 divisions per MUFU.RCP ----
    float ssim_acc = 0.f;
    float Nacc = 0.f, Dacc = 1.f;
    int   cnt = 0;
    #pragma unroll
    for (int o = 0; o < VOUT; o++) {
        const int tr  = rb + o;
        const int gro = by * TH + tr;
        if (tr < TH && gro < IMG) {
            float2 m = unpack2(b1[o]);   // (mu_s, mu_d)
            float2 e = unpack2(b2[o]);   // (E[s^2], E[d^2])
            float mus2 = m.x * m.x;
            float mud2 = m.y * m.y;
            float mu12   = 0.25f * (mus2 - mud2);
            float musum  = 0.5f  * (mus2 + mud2);
            float sig12  = 0.25f * (e.x - e.y) - mu12;
            float sigsum = 0.5f  * (e.x + e.y) - musum;
            float num = (2.f * mu12 + C1f) * (2.f * sig12 + C2f);
            float den = (musum + C1f) * (sigsum + C2f);
            Nacc = Nacc * den + num * Dacc;
            Dacc = Dacc * den;
            cnt++;
            if (cnt == 4) {
                ssim_acc = fmaf(Nacc, frcp(Dacc), ssim_acc);
                Nacc = 0.f; Dacc = 1.f; cnt = 0;
            }
        }
    }
    if (cnt > 0)
        ssim_acc = fmaf(Nacc, frcp(Dacc), ssim_acc);

    // ---- block reduction -> deterministic fixed-point atomics ----
    #pragma unroll
    for (int off = 16; off > 0; off >>= 1) {
        ssim_acc += __shfl_down_sync(0xffffffffu, ssim_acc, off);
        mse_acc  += __shfl_down_sync(0xffffffffu, mse_acc,  off);
    }
    if ((tid & 31) == 0) {
        red[tid >> 5]       = ssim_acc;
        red[8 + (tid >> 5)] = mse_acc;
    }
    __syncthreads();
    if (tid == 0) {
        float ss = 0.f, mm = 0.f;
        #pragma unroll
        for (int w2 = 0; w2 < 8; w2++) { ss += red[w2]; mm += red[8 + w2]; }
        atomicAdd(&g_acc[0], (ull)__double2ll_rn((double)ss * FXS));
        atomicAdd(&g_acc[1], (ull)__double2ll_rn((double)mm * FXS));
        __threadfence();
        unsigned t = atomicAdd(&g_count, 1u);
        s_last = (t == NBLOCKS - 1);
    }
    __syncthreads();

    // ---- last block finalizes and resets for next graph replay ----
    if (s_last && tid == 0) {
        __threadfence();
        ull a0  = atomicExch(&g_acc[0], 0ull);
        ull a1v = atomicExch(&g_acc[1], 0ull);
        atomicExch(&g_count, 0u);
        double inv = 1.0 / (NPIX * FXS);
        double ss = (double)(long long)a0 * inv;
        double mm = (double)(long long)a1v * inv;
        out[0] = (float)(1.0 - ss + mm);
    }
}

extern "C" void kernel_launch(void* const* d_in, const int* in_sizes, int n_in,
                              void* d_out, int out_size)
{
    const float* x = (const float*)d_in[0];
    const float* y = (const float*)d_in[1];
    float* out = (float*)d_out;

    cudaFuncSetAttribute(loss_kernel,
                         cudaFuncAttributeMaxDynamicSharedMemorySize, SMEMB);

    dim3 grid(NBX, NBY, NPL);   // (16, 5, 48) = 3840 blocks
    loss_kernel<<<grid, 256, SMEMB>>>(x, y, out);
}